// round 6
// baseline (speedup 1.0000x reference)
#include <cuda_runtime.h>
#include <cuda_fp16.h>
#include <math.h>

// Problem constants
#define NG    2048   // glimpses
#define NPG   512    // points per glimpse
#define CPG   128    // level-1 clusters per glimpse
#define CPG2  32     // level-2 clusters per glimpse

// Output layout (float32)
#define OFF_ZWHAT 0
#define OFF_ZMASK 131072
#define OFF_MU    262144
#define OFF_SIGMA 524288
#define OFF_F     786432

struct __align__(16) Smem {
    float w1l[64];      // [4][16]
    float b1l[16];
    float b1g[32];
    float b2l[64];
    float w1g[512];     // [16][32]
    float pos1l[384];   // [128][3]
    float pos2l[96];    // [32][3]
    int   idx1[128];    // local level-2 cluster per level-1 cluster
    int   cur[128];     // counts -> alloc cursors
    int   cur2[32];
    unsigned short ofs[128];
    unsigned short ofs2[32];
    unsigned short order[512];
    unsigned short order2[128];
    float agg[2048];    // means: stage1 [128][16], stage3b [32][64]
    float gsum[128];
    float fvec[256];
    float outv[256];
    union {             // 16 KB, disjoint lifetimes
        float f1[4096];     // [128][32]  stage2 -> stage3a
        float f2[4096];     // [32][128]  stage4 -> stage5
    } A;
    union {             // 16 KB, disjoint lifetimes
        struct { float2 a[512]; float2 b[512]; } pts; // (rgb,px),(py,pz)
        __half2 h2[4096];   // [128][32xhalf2] stage3a -> stage3b
        float   psum[1024]; // [8][128]   stage5
    } B;
};

// branchless celu: exact for x>0 (expf(0)==1), expf path for x<=0
__device__ __forceinline__ float celu1(float x) {
    return fmaxf(x, 0.0f) + (__expf(fminf(x, 0.0f)) - 1.0f);
}

#define FMA4(Aacc, xs, wv) \
    { Aacc[0] = fmaf((xs), (wv).x, Aacc[0]); Aacc[1] = fmaf((xs), (wv).y, Aacc[1]); \
      Aacc[2] = fmaf((xs), (wv).z, Aacc[2]); Aacc[3] = fmaf((xs), (wv).w, Aacc[3]); }

__global__ void __launch_bounds__(256, 4)
vae_fused_kernel(const float* __restrict__ rgb,  const float* __restrict__ pos,
                 const float* __restrict__ pos1, const float* __restrict__ pos2,
                 const int*   __restrict__ oi0,  const int* __restrict__ oi1,
                 const float* __restrict__ eps,
                 const float* __restrict__ W1l, const float* __restrict__ b1l,
                 const float* __restrict__ W1g, const float* __restrict__ b1g,
                 const float* __restrict__ W2l, const float* __restrict__ b2l,
                 const float* __restrict__ W2g, const float* __restrict__ b2g,
                 const float* __restrict__ W3l, const float* __restrict__ b3l,
                 const float* __restrict__ W3g, const float* __restrict__ b3g,
                 const float* __restrict__ Wlin, const float* __restrict__ blin,
                 float* __restrict__ out)
{
    extern __shared__ unsigned char smem_raw[];
    Smem& s = *reinterpret_cast<Smem*>(smem_raw);
    const int tid  = threadIdx.x;
    const int lane = tid & 31;
    const int g    = blockIdx.x;

    // ---------------- preload small weights / geometry, zero counters -------
    for (int i = tid; i < 64;  i += 256) s.w1l[i] = W1l[i];
    if (tid < 16) s.b1l[tid] = b1l[tid];
    if (tid < 32) s.b1g[tid] = b1g[tid];
    if (tid < 64) s.b2l[tid] = b2l[tid];
    for (int i = tid; i < 512; i += 256) s.w1g[i] = W1g[i];
    for (int i = tid; i < 384; i += 256) s.pos1l[i] = pos1[(size_t)g * 384 + i];
    if (tid < 96)  s.pos2l[tid] = pos2[(size_t)g * 96 + tid];
    if (tid < 128) s.cur[tid] = 0;
    if (tid < 32)  s.cur2[tid] = 0;
    __syncthreads();

    // ---------------- count phase -------------------------------------------
    if (tid < 128) {
        const int c2 = (int)(oi1[(size_t)g * 128 + tid] - g * CPG2);
        s.idx1[tid] = c2;
        atomicAdd(&s.cur2[c2], 1);
    }
    for (int p = tid; p < NPG; p += 256) {
        const size_t e = (size_t)g * NPG + p;
        float2 pa, pb;
        pa.x = rgb[e];
        pa.y = pos[e * 3 + 0];
        pb.x = pos[e * 3 + 1];
        pb.y = pos[e * 3 + 2];
        s.B.pts.a[p] = pa;
        s.B.pts.b[p] = pb;
        atomicAdd(&s.cur[oi0[e] - g * CPG], 1);
    }
    __syncthreads();

    // ---------------- prefix sums; cur becomes alloc cursor -----------------
    if (tid < 32) {
        int v0 = s.cur[lane * 4 + 0], v1 = s.cur[lane * 4 + 1];
        int v2 = s.cur[lane * 4 + 2], v3 = s.cur[lane * 4 + 3];
        int lsum = v0 + v1 + v2 + v3;
        int sc = lsum;
        #pragma unroll
        for (int off = 1; off < 32; off <<= 1) {
            int n = __shfl_up_sync(0xffffffffu, sc, off);
            if (lane >= off) sc += n;
        }
        int e0 = sc - lsum;
        int e1 = e0 + v0, e2 = e1 + v1, e3 = e2 + v2;
        s.ofs[lane * 4 + 0] = (unsigned short)e0; s.cur[lane * 4 + 0] = e0;
        s.ofs[lane * 4 + 1] = (unsigned short)e1; s.cur[lane * 4 + 1] = e1;
        s.ofs[lane * 4 + 2] = (unsigned short)e2; s.cur[lane * 4 + 2] = e2;
        s.ofs[lane * 4 + 3] = (unsigned short)e3; s.cur[lane * 4 + 3] = e3;
    } else if (tid < 64) {
        int v = s.cur2[lane];
        int sc = v;
        #pragma unroll
        for (int off = 1; off < 32; off <<= 1) {
            int n = __shfl_up_sync(0xffffffffu, sc, off);
            if (lane >= off) sc += n;
        }
        s.ofs2[lane] = (unsigned short)(sc - v);
        s.cur2[lane] = sc - v;
    }
    __syncthreads();

    // ---------------- scatter passes ----------------------------------------
    for (int p = tid; p < NPG; p += 256) {
        const int c = oi0[(size_t)g * NPG + p] - g * CPG;
        const int slot = atomicAdd(&s.cur[c], 1);
        s.order[slot] = (unsigned short)p;
    }
    if (tid < 128) {
        const int slot = atomicAdd(&s.cur2[s.idx1[tid]], 1);
        s.order2[slot] = (unsigned short)tid;
    }
    __syncthreads();

    // ---------------- stage 1: gather edge MLP (4 -> 16) + mean -------------
    {
        const int c    = tid >> 1;       // 128 clusters x 2 threads
        const int half = tid & 1;        // 8 features each
        const int beg = (int)s.ofs[c];
        const int n   = s.cur[c] - beg;
        const float cx = s.pos1l[c * 3 + 0];
        const float cy = s.pos1l[c * 3 + 1];
        const float cz = s.pos1l[c * 3 + 2];
        float wb[8], w0r[8], w1r[8], w2r[8], w3r[8];
        #pragma unroll
        for (int j8 = 0; j8 < 8; j8++) {
            const int j = half * 8 + j8;
            wb[j8]  = s.b1l[j];
            w0r[j8] = s.w1l[j];
            w1r[j8] = s.w1l[16 + j];
            w2r[j8] = s.w1l[32 + j];
            w3r[j8] = s.w1l[48 + j];
        }
        float acc[8];
        #pragma unroll
        for (int j8 = 0; j8 < 8; j8++) acc[j8] = 0.0f;
        for (int i = 0; i < n; i++) {
            const int p = (int)s.order[beg + i];
            const float2 pa = s.B.pts.a[p];
            const float2 pb = s.B.pts.b[p];
            const float rx = pa.y - cx, ry = pb.x - cy, rz = pb.y - cz;
            #pragma unroll
            for (int j8 = 0; j8 < 8; j8++) {
                float a = wb[j8];
                a = fmaf(pa.x, w0r[j8], a);
                a = fmaf(rx,   w1r[j8], a);
                a = fmaf(ry,   w2r[j8], a);
                a = fmaf(rz,   w3r[j8], a);
                acc[j8] += celu1(a);
            }
        }
        const float inv = 1.0f / fmaxf((float)n, 1.0f);
        #pragma unroll
        for (int j8 = 0; j8 < 8; j8++)
            s.agg[c * 16 + half * 8 + j8] = acc[j8] * inv;
    }
    __syncthreads();

    // ---------------- stage 2: f1 = celu(mean1 @ W1g + b1g)  [128][32] ------
    {
        const int jq = tid & 7;
        const int cg = tid >> 3;
        const float4* Wq = reinterpret_cast<const float4*>(s.w1g); // [16][8]
        float acc[4][4];
        #pragma unroll
        for (int c4 = 0; c4 < 4; c4++)
            #pragma unroll
            for (int u = 0; u < 4; u++) acc[c4][u] = s.b1g[jq * 4 + u];
        #pragma unroll
        for (int k = 0; k < 16; k++) {
            const float4 wv = Wq[k * 8 + jq];
            #pragma unroll
            for (int c4 = 0; c4 < 4; c4++) {
                const float x = s.agg[(cg * 4 + c4) * 16 + k];
                FMA4(acc[c4], x, wv);
            }
        }
        #pragma unroll
        for (int c4 = 0; c4 < 4; c4++)
            #pragma unroll
            for (int u = 0; u < 4; u++)
                s.A.f1[(cg * 4 + c4) * 32 + jq * 4 + u] = celu1(acc[c4][u]);
    }
    __syncthreads();

    // ---------------- stage 3a: edge MLP (35 -> 64) into h2 (fp16) ----------
    // Two passes of 4 edges each to keep register pressure under 64.
    {
        const int jq = tid & 15;         // 16 quads -> 64 outputs
        const int eg = tid >> 4;         // 16 groups x 8 edges
        const float4* Wq  = reinterpret_cast<const float4*>(W2l);   // [35][16]
        const float4* F1q = reinterpret_cast<const float4*>(s.A.f1);// [128][8]
        const float4 bb = reinterpret_cast<const float4*>(s.b2l)[jq];
        #pragma unroll
        for (int pass = 0; pass < 2; pass++) {
            const int ebase = eg * 8 + pass * 4;
            float acc[4][4];
            #pragma unroll
            for (int e = 0; e < 4; e++) {
                acc[e][0] = bb.x; acc[e][1] = bb.y; acc[e][2] = bb.z; acc[e][3] = bb.w;
            }
            #pragma unroll
            for (int kq = 0; kq < 8; kq++) {
                const float4 wa = Wq[(kq * 4 + 0) * 16 + jq];
                const float4 wb = Wq[(kq * 4 + 1) * 16 + jq];
                const float4 wc = Wq[(kq * 4 + 2) * 16 + jq];
                const float4 wd = Wq[(kq * 4 + 3) * 16 + jq];
                #pragma unroll
                for (int e = 0; e < 4; e++) {
                    const float4 x = F1q[(ebase + e) * 8 + kq];
                    FMA4(acc[e], x.x, wa);
                    FMA4(acc[e], x.y, wb);
                    FMA4(acc[e], x.z, wc);
                    FMA4(acc[e], x.w, wd);
                }
            }
            #pragma unroll
            for (int k2 = 0; k2 < 3; k2++) {
                const float4 wv = Wq[(32 + k2) * 16 + jq];
                #pragma unroll
                for (int e = 0; e < 4; e++) {
                    const int ee = ebase + e;
                    const float r = s.pos1l[ee * 3 + k2] - s.pos2l[s.idx1[ee] * 3 + k2];
                    FMA4(acc[e], r, wv);
                }
            }
            #pragma unroll
            for (int e = 0; e < 4; e++) {
                const int ee = ebase + e;
                const __half2 h0 = __floats2half2_rn(celu1(acc[e][0]), celu1(acc[e][1]));
                const __half2 h1 = __floats2half2_rn(celu1(acc[e][2]), celu1(acc[e][3]));
                float2 pk;
                pk.x = __uint_as_float(*reinterpret_cast<const unsigned int*>(&h0));
                pk.y = __uint_as_float(*reinterpret_cast<const unsigned int*>(&h1));
                *reinterpret_cast<float2*>(&s.B.h2[ee * 32 + jq * 2]) = pk;
            }
        }
    }
    __syncthreads();

    // ---------------- stage 3b: gather-reduce h2 -> mean2 [32][64] ----------
    {
        const int c2 = tid >> 3;
        const int f8 = tid & 7;          // 8 features each (4 half2)
        const int beg = (int)s.ofs2[c2];
        const int n   = s.cur2[c2] - beg;
        float acc[8];
        #pragma unroll
        for (int k = 0; k < 8; k++) acc[k] = 0.0f;
        for (int i = 0; i < n; i++) {
            const int e = (int)s.order2[beg + i];
            const float4 raw = *reinterpret_cast<const float4*>(&s.B.h2[e * 32 + f8 * 4]);
            const __half2 h0 = *reinterpret_cast<const __half2*>(&raw.x);
            const __half2 h1 = *reinterpret_cast<const __half2*>(&raw.y);
            const __half2 h2v = *reinterpret_cast<const __half2*>(&raw.z);
            const __half2 h3 = *reinterpret_cast<const __half2*>(&raw.w);
            const float2 f0 = __half22float2(h0);
            const float2 f1v = __half22float2(h1);
            const float2 f2v = __half22float2(h2v);
            const float2 f3 = __half22float2(h3);
            acc[0] += f0.x; acc[1] += f0.y; acc[2] += f1v.x; acc[3] += f1v.y;
            acc[4] += f2v.x; acc[5] += f2v.y; acc[6] += f3.x; acc[7] += f3.y;
        }
        const float inv = 1.0f / fmaxf((float)n, 1.0f);
        float4 o0, o1;
        o0.x = acc[0] * inv; o0.y = acc[1] * inv; o0.z = acc[2] * inv; o0.w = acc[3] * inv;
        o1.x = acc[4] * inv; o1.y = acc[5] * inv; o1.z = acc[6] * inv; o1.w = acc[7] * inv;
        reinterpret_cast<float4*>(&s.agg[c2 * 64 + f8 * 8])[0] = o0;
        reinterpret_cast<float4*>(&s.agg[c2 * 64 + f8 * 8])[1] = o1;
    }
    __syncthreads();

    // ---------------- stage 4: f2 = celu(mean2 @ W2g + b2g)  [32][128] ------
    {
        const int jq = tid & 31;
        const int cg = tid >> 5;
        const float4* Wq = reinterpret_cast<const float4*>(W2g);   // [64][32]
        const float4* Aq = reinterpret_cast<const float4*>(s.agg); // [32][16]
        const float4 bb = reinterpret_cast<const float4*>(b2g)[jq];
        float acc[4][4];
        #pragma unroll
        for (int c4 = 0; c4 < 4; c4++) {
            acc[c4][0] = bb.x; acc[c4][1] = bb.y; acc[c4][2] = bb.z; acc[c4][3] = bb.w;
        }
        #pragma unroll 4
        for (int kq = 0; kq < 16; kq++) {
            const float4 wa = Wq[(kq * 4 + 0) * 32 + jq];
            const float4 wb = Wq[(kq * 4 + 1) * 32 + jq];
            const float4 wc = Wq[(kq * 4 + 2) * 32 + jq];
            const float4 wd = Wq[(kq * 4 + 3) * 32 + jq];
            #pragma unroll
            for (int c4 = 0; c4 < 4; c4++) {
                const float4 x = Aq[(cg * 4 + c4) * 16 + kq];
                FMA4(acc[c4], x.x, wa);
                FMA4(acc[c4], x.y, wb);
                FMA4(acc[c4], x.z, wc);
                FMA4(acc[c4], x.w, wd);
            }
        }
        #pragma unroll
        for (int c4 = 0; c4 < 4; c4++)
            #pragma unroll
            for (int u = 0; u < 4; u++)
                s.A.f2[(cg * 4 + c4) * 128 + jq * 4 + u] = celu1(acc[c4][u]);
    }
    __syncthreads();

    // ---------------- stage 5: level-3 edge MLP (131 -> 128) + mean ---------
    {
        const int jq = tid & 31;
        const int eg = tid >> 5;
        const float4* Wq  = reinterpret_cast<const float4*>(W3l);   // [131][32]
        const float4* F2q = reinterpret_cast<const float4*>(s.A.f2);// [32][32]
        const float4 bb = reinterpret_cast<const float4*>(b3l)[jq];
        float acc[4][4];
        #pragma unroll
        for (int e = 0; e < 4; e++) {
            acc[e][0] = bb.x; acc[e][1] = bb.y; acc[e][2] = bb.z; acc[e][3] = bb.w;
        }
        #pragma unroll 4
        for (int kq = 0; kq < 32; kq++) {
            const float4 wa = Wq[(kq * 4 + 0) * 32 + jq];
            const float4 wb = Wq[(kq * 4 + 1) * 32 + jq];
            const float4 wc = Wq[(kq * 4 + 2) * 32 + jq];
            const float4 wd = Wq[(kq * 4 + 3) * 32 + jq];
            #pragma unroll
            for (int e = 0; e < 4; e++) {
                const float4 x = F2q[(eg * 4 + e) * 32 + kq];
                FMA4(acc[e], x.x, wa);
                FMA4(acc[e], x.y, wb);
                FMA4(acc[e], x.z, wc);
                FMA4(acc[e], x.w, wd);
            }
        }
        #pragma unroll
        for (int k2 = 0; k2 < 3; k2++) {
            const float4 wv = Wq[(128 + k2) * 32 + jq];
            #pragma unroll
            for (int e = 0; e < 4; e++) {
                const float r = s.pos2l[(eg * 4 + e) * 3 + k2];
                FMA4(acc[e], r, wv);
            }
        }
        float4 pv;
        pv.x = celu1(acc[0][0]) + celu1(acc[1][0]) + celu1(acc[2][0]) + celu1(acc[3][0]);
        pv.y = celu1(acc[0][1]) + celu1(acc[1][1]) + celu1(acc[2][1]) + celu1(acc[3][1]);
        pv.z = celu1(acc[0][2]) + celu1(acc[1][2]) + celu1(acc[2][2]) + celu1(acc[3][2]);
        pv.w = celu1(acc[0][3]) + celu1(acc[1][3]) + celu1(acc[2][3]) + celu1(acc[3][3]);
        reinterpret_cast<float4*>(&s.B.psum[eg * 128 + jq * 4])[0] = pv;
    }
    __syncthreads();
    if (tid < 128) {
        float sum = 0.0f;
        #pragma unroll
        for (int e = 0; e < 8; e++) sum += s.B.psum[e * 128 + tid];
        s.gsum[tid] = sum;
    }
    __syncthreads();

    // ---------------- stage 6: f = celu((gsum/32) @ W3g + b3g)  [256] -------
    {
        const int j = tid;
        float sum = 0.0f;
        #pragma unroll 8
        for (int k = 0; k < 128; k++)
            sum = fmaf(s.gsum[k], W3g[k * 256 + j], sum);
        const float fv = celu1(fmaf(sum, 0.03125f, b3g[j]));
        s.fvec[j] = fv;
        out[OFF_F + (size_t)g * 256 + j] = fv;
    }
    __syncthreads();

    // ---------------- stage 7: out = f @ Wlin + blin, rsample ---------------
    {
        const int j = tid;
        float acc = blin[j];
        #pragma unroll 8
        for (int k = 0; k < 256; k++)
            acc = fmaf(s.fvec[k], Wlin[k * 256 + j], acc);
        s.outv[j] = acc;
    }
    __syncthreads();

    if (tid < 128) {
        const float mu = s.outv[tid];
        const float sg = s.outv[128 + tid];
        const float sigma = fmaxf(sg, 0.0f) + log1pf(__expf(-fabsf(sg)));
        const float z = fmaf(sigma, eps[(size_t)g * 128 + tid], mu);
        out[OFF_MU    + (size_t)g * 128 + tid] = mu;
        out[OFF_SIGMA + (size_t)g * 128 + tid] = sigma;
        if (tid < 64) out[OFF_ZWHAT + (size_t)g * 64 + tid] = z;
        else          out[OFF_ZMASK + (size_t)g * 64 + (tid - 64)] = z;
    }
}

extern "C" void kernel_launch(void* const* d_in, const int* in_sizes, int n_in,
                              void* d_out, int out_size)
{
    const float* rgb  = (const float*)d_in[0];
    const float* pos  = (const float*)d_in[1];
    const float* pos1 = (const float*)d_in[2];
    const float* pos2 = (const float*)d_in[3];
    const int*   oi0  = (const int*)  d_in[4];
    const int*   oi1  = (const int*)  d_in[5];
    const float* eps  = (const float*)d_in[7];
    const float* W1l  = (const float*)d_in[8];
    const float* b1l  = (const float*)d_in[9];
    const float* W1g  = (const float*)d_in[10];
    const float* b1g  = (const float*)d_in[11];
    const float* W2l  = (const float*)d_in[12];
    const float* b2l  = (const float*)d_in[13];
    const float* W2g  = (const float*)d_in[14];
    const float* b2g  = (const float*)d_in[15];
    const float* W3l  = (const float*)d_in[16];
    const float* b3l  = (const float*)d_in[17];
    const float* W3g  = (const float*)d_in[18];
    const float* b3g  = (const float*)d_in[19];
    const float* Wlin = (const float*)d_in[20];
    const float* blin = (const float*)d_in[21];
    float* out = (float*)d_out;

    cudaFuncSetAttribute(vae_fused_kernel,
                         cudaFuncAttributeMaxDynamicSharedMemorySize,
                         (int)sizeof(Smem));
    vae_fused_kernel<<<NG, 256, sizeof(Smem)>>>(
        rgb, pos, pos1, pos2, oi0, oi1, eps,
        W1l, b1l, W1g, b1g, W2l, b2l, W2g, b2g,
        W3l, b3l, W3g, b3g, Wlin, blin, out);
}

// round 7
// speedup vs baseline: 1.7374x; 1.7374x over previous
#include <cuda_runtime.h>
#include <cuda_fp16.h>
#include <math.h>

// Problem constants
#define NG    2048   // glimpses
#define NPG   512    // points per glimpse
#define CPG   128    // level-1 clusters per glimpse
#define CPG2  32     // level-2 clusters per glimpse

// Output layout (float32)
#define OFF_ZWHAT 0
#define OFF_ZMASK 131072
#define OFF_MU    262144
#define OFF_SIGMA 524288
#define OFF_F     786432

struct __align__(16) Smem {
    float w1l[64];      // [4][16]
    float b1l[16];
    float b1g[32];
    float b2l[64];
    float w1g[512];     // [16][32]
    float pos1l[384];   // [128][3]      (per-glimpse, reloaded)
    float pos2l2[192];  // [2][32][3]    (both glimpses)
    int   idx1[128];
    int   cur[128];
    int   cur2[32];
    unsigned short ofs[128];
    unsigned short ofs2[32];
    unsigned short order[512];
    unsigned short order2[128];
    float agg[2048];    // stage1 mean [128][16] (per-glimpse)
    float mean2[4096];  // [2][32][64]  fp32
    float gsum[256];    // [2][128]
    float fvec[512];    // [2][256]
    float outv[512];    // [2][256]
    union {             // 16 KB
        float f1[4096];     // [128][32]  per-glimpse stage2->3a
        float psum[2048];   // [2][8][128] joint stage5
    } A;
    union {             // 16 KB
        float4  pts[512];   // per-glimpse load->stage1
        __half2 h2[4096];   // [128][32]  per-glimpse stage3a->3b
        __half2 f2h[4096];  // [2][32][64] joint stage4->5
    } B;
};

// branchless celu: exact for x>0 (expf(0)==1)
__device__ __forceinline__ float celu1(float x) {
    return fmaxf(x, 0.0f) + (__expf(fminf(x, 0.0f)) - 1.0f);
}

#define FMA4(Aacc, xs, wv) \
    { Aacc[0] = fmaf((xs), (wv).x, Aacc[0]); Aacc[1] = fmaf((xs), (wv).y, Aacc[1]); \
      Aacc[2] = fmaf((xs), (wv).z, Aacc[2]); Aacc[3] = fmaf((xs), (wv).w, Aacc[3]); }

__global__ void __launch_bounds__(256, 3)
vae_fused_kernel(const float* __restrict__ rgb,  const float* __restrict__ pos,
                 const float* __restrict__ pos1, const float* __restrict__ pos2,
                 const int*   __restrict__ oi0,  const int* __restrict__ oi1,
                 const float* __restrict__ eps,
                 const float* __restrict__ W1l, const float* __restrict__ b1l,
                 const float* __restrict__ W1g, const float* __restrict__ b1g,
                 const float* __restrict__ W2l, const float* __restrict__ b2l,
                 const float* __restrict__ W2g, const float* __restrict__ b2g,
                 const float* __restrict__ W3l, const float* __restrict__ b3l,
                 const float* __restrict__ W3g, const float* __restrict__ b3g,
                 const float* __restrict__ Wlin, const float* __restrict__ blin,
                 float* __restrict__ out)
{
    extern __shared__ unsigned char smem_raw[];
    Smem& s = *reinterpret_cast<Smem*>(smem_raw);
    const int tid  = threadIdx.x;
    const int lane = tid & 31;
    const int g0   = blockIdx.x * 2;

    // ---------------- preamble: weights + both glimpses' level-2 centers ----
    for (int i = tid; i < 64;  i += 256) s.w1l[i] = W1l[i];
    if (tid < 16) s.b1l[tid] = b1l[tid];
    if (tid < 32) s.b1g[tid] = b1g[tid];
    if (tid < 64) s.b2l[tid] = b2l[tid];
    for (int i = tid; i < 512; i += 256) s.w1g[i] = W1g[i];
    if (tid < 192) s.pos2l2[tid] = pos2[(size_t)g0 * 96 + tid];

    // ============ per-glimpse stages 1-3 (sequential, buffers reused) =======
    for (int gi = 0; gi < 2; gi++) {
        const int g = g0 + gi;
        __syncthreads();
        if (tid < 128) s.cur[tid] = 0;
        if (tid < 32)  s.cur2[tid] = 0;
        for (int i = tid; i < 384; i += 256) s.pos1l[i] = pos1[(size_t)g * 384 + i];
        __syncthreads();

        // count phase
        if (tid < 128) {
            const int c2 = (int)(oi1[(size_t)g * 128 + tid] - g * CPG2);
            s.idx1[tid] = c2;
            atomicAdd(&s.cur2[c2], 1);
        }
        for (int p = tid; p < NPG; p += 256) {
            const size_t e = (size_t)g * NPG + p;
            float4 pt;
            pt.x = rgb[e];
            pt.y = pos[e * 3 + 0];
            pt.z = pos[e * 3 + 1];
            pt.w = pos[e * 3 + 2];
            s.B.pts[p] = pt;
            atomicAdd(&s.cur[oi0[e] - g * CPG], 1);
        }
        __syncthreads();

        // prefix sums; cur becomes alloc cursor
        if (tid < 32) {
            int v0 = s.cur[lane * 4 + 0], v1 = s.cur[lane * 4 + 1];
            int v2 = s.cur[lane * 4 + 2], v3 = s.cur[lane * 4 + 3];
            int lsum = v0 + v1 + v2 + v3;
            int sc = lsum;
            #pragma unroll
            for (int off = 1; off < 32; off <<= 1) {
                int n = __shfl_up_sync(0xffffffffu, sc, off);
                if (lane >= off) sc += n;
            }
            int e0 = sc - lsum;
            int e1 = e0 + v0, e2 = e1 + v1, e3 = e2 + v2;
            s.ofs[lane * 4 + 0] = (unsigned short)e0; s.cur[lane * 4 + 0] = e0;
            s.ofs[lane * 4 + 1] = (unsigned short)e1; s.cur[lane * 4 + 1] = e1;
            s.ofs[lane * 4 + 2] = (unsigned short)e2; s.cur[lane * 4 + 2] = e2;
            s.ofs[lane * 4 + 3] = (unsigned short)e3; s.cur[lane * 4 + 3] = e3;
        } else if (tid < 64) {
            int v = s.cur2[lane];
            int sc = v;
            #pragma unroll
            for (int off = 1; off < 32; off <<= 1) {
                int n = __shfl_up_sync(0xffffffffu, sc, off);
                if (lane >= off) sc += n;
            }
            s.ofs2[lane] = (unsigned short)(sc - v);
            s.cur2[lane] = sc - v;
        }
        __syncthreads();

        // scatter passes
        for (int p = tid; p < NPG; p += 256) {
            const int c = oi0[(size_t)g * NPG + p] - g * CPG;
            const int slot = atomicAdd(&s.cur[c], 1);
            s.order[slot] = (unsigned short)p;
        }
        if (tid < 128) {
            const int slot = atomicAdd(&s.cur2[s.idx1[tid]], 1);
            s.order2[slot] = (unsigned short)tid;
        }
        __syncthreads();

        // stage 1: gather edge MLP (4 -> 16) + mean
        {
            const int c    = tid >> 1;
            const int half = tid & 1;
            const int beg = (int)s.ofs[c];
            const int n   = s.cur[c] - beg;
            const float cx = s.pos1l[c * 3 + 0];
            const float cy = s.pos1l[c * 3 + 1];
            const float cz = s.pos1l[c * 3 + 2];
            float wb[8], w0r[8], w1r[8], w2r[8], w3r[8];
            #pragma unroll
            for (int j8 = 0; j8 < 8; j8++) {
                const int j = half * 8 + j8;
                wb[j8]  = s.b1l[j];
                w0r[j8] = s.w1l[j];
                w1r[j8] = s.w1l[16 + j];
                w2r[j8] = s.w1l[32 + j];
                w3r[j8] = s.w1l[48 + j];
            }
            float acc[8];
            #pragma unroll
            for (int j8 = 0; j8 < 8; j8++) acc[j8] = 0.0f;
            for (int i = 0; i < n; i++) {
                const float4 pt = s.B.pts[(int)s.order[beg + i]];
                const float rx = pt.y - cx, ry = pt.z - cy, rz = pt.w - cz;
                #pragma unroll
                for (int j8 = 0; j8 < 8; j8++) {
                    float a = wb[j8];
                    a = fmaf(pt.x, w0r[j8], a);
                    a = fmaf(rx,   w1r[j8], a);
                    a = fmaf(ry,   w2r[j8], a);
                    a = fmaf(rz,   w3r[j8], a);
                    acc[j8] += celu1(a);
                }
            }
            const float inv = 1.0f / fmaxf((float)n, 1.0f);
            #pragma unroll
            for (int j8 = 0; j8 < 8; j8++)
                s.agg[c * 16 + half * 8 + j8] = acc[j8] * inv;
        }
        __syncthreads();

        // stage 2: f1 = celu(mean1 @ W1g + b1g)  [128][32]
        {
            const int jq = tid & 7;
            const int cg = tid >> 3;
            const float4* Wq = reinterpret_cast<const float4*>(s.w1g); // [16][8]
            float acc[4][4];
            #pragma unroll
            for (int c4 = 0; c4 < 4; c4++)
                #pragma unroll
                for (int u = 0; u < 4; u++) acc[c4][u] = s.b1g[jq * 4 + u];
            #pragma unroll
            for (int k = 0; k < 16; k++) {
                const float4 wv = Wq[k * 8 + jq];
                #pragma unroll
                for (int c4 = 0; c4 < 4; c4++) {
                    const float x = s.agg[(cg * 4 + c4) * 16 + k];
                    FMA4(acc[c4], x, wv);
                }
            }
            #pragma unroll
            for (int c4 = 0; c4 < 4; c4++)
                #pragma unroll
                for (int u = 0; u < 4; u++)
                    s.A.f1[(cg * 4 + c4) * 32 + jq * 4 + u] = celu1(acc[c4][u]);
        }
        __syncthreads();

        // stage 3a: edge MLP (35 -> 64) into h2 (fp16), W2l from global
        {
            const int jq = tid & 15;
            const int eg = tid >> 4;
            const float4* Wq  = reinterpret_cast<const float4*>(W2l);   // [35][16]
            const float4* F1q = reinterpret_cast<const float4*>(s.A.f1);// [128][8]
            const float4 bb = reinterpret_cast<const float4*>(s.b2l)[jq];
            float acc[8][4];
            #pragma unroll
            for (int e = 0; e < 8; e++) {
                acc[e][0] = bb.x; acc[e][1] = bb.y; acc[e][2] = bb.z; acc[e][3] = bb.w;
            }
            #pragma unroll
            for (int kq = 0; kq < 8; kq++) {
                const float4 wa = Wq[(kq * 4 + 0) * 16 + jq];
                const float4 wb = Wq[(kq * 4 + 1) * 16 + jq];
                const float4 wc = Wq[(kq * 4 + 2) * 16 + jq];
                const float4 wd = Wq[(kq * 4 + 3) * 16 + jq];
                #pragma unroll
                for (int e = 0; e < 8; e++) {
                    const float4 x = F1q[(eg * 8 + e) * 8 + kq];
                    FMA4(acc[e], x.x, wa);
                    FMA4(acc[e], x.y, wb);
                    FMA4(acc[e], x.z, wc);
                    FMA4(acc[e], x.w, wd);
                }
            }
            #pragma unroll
            for (int k2 = 0; k2 < 3; k2++) {
                const float4 wv = Wq[(32 + k2) * 16 + jq];
                #pragma unroll
                for (int e = 0; e < 8; e++) {
                    const int ee = eg * 8 + e;
                    const float r = s.pos1l[ee * 3 + k2]
                                  - s.pos2l2[gi * 96 + s.idx1[ee] * 3 + k2];
                    FMA4(acc[e], r, wv);
                }
            }
            #pragma unroll
            for (int e = 0; e < 8; e++) {
                const int ee = eg * 8 + e;
                const __half2 h0 = __floats2half2_rn(celu1(acc[e][0]), celu1(acc[e][1]));
                const __half2 h1 = __floats2half2_rn(celu1(acc[e][2]), celu1(acc[e][3]));
                float2 pk;
                pk.x = __uint_as_float(*reinterpret_cast<const unsigned int*>(&h0));
                pk.y = __uint_as_float(*reinterpret_cast<const unsigned int*>(&h1));
                *reinterpret_cast<float2*>(&s.B.h2[ee * 32 + jq * 2]) = pk;
            }
        }
        __syncthreads();

        // stage 3b: gather-reduce h2 -> mean2[gi] [32][64]
        {
            const int c2 = tid >> 3;
            const int f8 = tid & 7;
            const int beg = (int)s.ofs2[c2];
            const int n   = s.cur2[c2] - beg;
            float acc[8];
            #pragma unroll
            for (int k = 0; k < 8; k++) acc[k] = 0.0f;
            for (int i = 0; i < n; i++) {
                const int e = (int)s.order2[beg + i];
                const float4 raw = *reinterpret_cast<const float4*>(&s.B.h2[e * 32 + f8 * 4]);
                const __half2 h0 = *reinterpret_cast<const __half2*>(&raw.x);
                const __half2 h1 = *reinterpret_cast<const __half2*>(&raw.y);
                const __half2 h2v = *reinterpret_cast<const __half2*>(&raw.z);
                const __half2 h3 = *reinterpret_cast<const __half2*>(&raw.w);
                const float2 f0 = __half22float2(h0);
                const float2 f1v = __half22float2(h1);
                const float2 f2v = __half22float2(h2v);
                const float2 f3 = __half22float2(h3);
                acc[0] += f0.x; acc[1] += f0.y; acc[2] += f1v.x; acc[3] += f1v.y;
                acc[4] += f2v.x; acc[5] += f2v.y; acc[6] += f3.x; acc[7] += f3.y;
            }
            const float inv = 1.0f / fmaxf((float)n, 1.0f);
            float4 o0, o1;
            o0.x = acc[0] * inv; o0.y = acc[1] * inv; o0.z = acc[2] * inv; o0.w = acc[3] * inv;
            o1.x = acc[4] * inv; o1.y = acc[5] * inv; o1.z = acc[6] * inv; o1.w = acc[7] * inv;
            reinterpret_cast<float4*>(&s.mean2[gi * 2048 + c2 * 64 + f8 * 8])[0] = o0;
            reinterpret_cast<float4*>(&s.mean2[gi * 2048 + c2 * 64 + f8 * 8])[1] = o1;
        }
    }
    __syncthreads();

    // ============ joint stages 4-7 (2 glimpses share every weight load) =====

    // stage 4: f2 = celu(mean2 @ W2g + b2g)  [2][32][128] -> fp16
    {
        const int jq = tid & 31;
        const int cg = tid >> 5;
        const float4* Wq = reinterpret_cast<const float4*>(W2g);      // [64][32]
        const float4* Aq = reinterpret_cast<const float4*>(s.mean2);  // [2][32][16]
        const float4 bb = reinterpret_cast<const float4*>(b2g)[jq];
        float acc[2][4][4];
        #pragma unroll
        for (int gi = 0; gi < 2; gi++)
            #pragma unroll
            for (int c4 = 0; c4 < 4; c4++) {
                acc[gi][c4][0] = bb.x; acc[gi][c4][1] = bb.y;
                acc[gi][c4][2] = bb.z; acc[gi][c4][3] = bb.w;
            }
        #pragma unroll 2
        for (int kq = 0; kq < 16; kq++) {
            const float4 wa = Wq[(kq * 4 + 0) * 32 + jq];
            const float4 wb = Wq[(kq * 4 + 1) * 32 + jq];
            const float4 wc = Wq[(kq * 4 + 2) * 32 + jq];
            const float4 wd = Wq[(kq * 4 + 3) * 32 + jq];
            #pragma unroll
            for (int gi = 0; gi < 2; gi++)
                #pragma unroll
                for (int c4 = 0; c4 < 4; c4++) {
                    const float4 x = Aq[gi * 512 + (cg * 4 + c4) * 16 + kq];
                    FMA4(acc[gi][c4], x.x, wa);
                    FMA4(acc[gi][c4], x.y, wb);
                    FMA4(acc[gi][c4], x.z, wc);
                    FMA4(acc[gi][c4], x.w, wd);
                }
        }
        #pragma unroll
        for (int gi = 0; gi < 2; gi++)
            #pragma unroll
            for (int c4 = 0; c4 < 4; c4++) {
                const __half2 h0 = __floats2half2_rn(celu1(acc[gi][c4][0]), celu1(acc[gi][c4][1]));
                const __half2 h1 = __floats2half2_rn(celu1(acc[gi][c4][2]), celu1(acc[gi][c4][3]));
                float2 pk;
                pk.x = __uint_as_float(*reinterpret_cast<const unsigned int*>(&h0));
                pk.y = __uint_as_float(*reinterpret_cast<const unsigned int*>(&h1));
                *reinterpret_cast<float2*>(
                    &s.B.f2h[(gi * 32 + cg * 4 + c4) * 64 + jq * 2]) = pk;
            }
    }
    __syncthreads();

    // stage 5: level-3 edge MLP (131 -> 128) + mean, both glimpses
    {
        const int jq = tid & 31;
        const int eg = tid >> 5;        // 8 groups x 4 edges
        const float4* Wq = reinterpret_cast<const float4*>(W3l);  // [131][32]
        const float4 bb = reinterpret_cast<const float4*>(b3l)[jq];
        float acc[2][4][4];
        #pragma unroll
        for (int gi = 0; gi < 2; gi++)
            #pragma unroll
            for (int e = 0; e < 4; e++) {
                acc[gi][e][0] = bb.x; acc[gi][e][1] = bb.y;
                acc[gi][e][2] = bb.z; acc[gi][e][3] = bb.w;
            }
        #pragma unroll 2
        for (int kq = 0; kq < 32; kq++) {
            const float4 wa = Wq[(kq * 4 + 0) * 32 + jq];
            const float4 wb = Wq[(kq * 4 + 1) * 32 + jq];
            const float4 wc = Wq[(kq * 4 + 2) * 32 + jq];
            const float4 wd = Wq[(kq * 4 + 3) * 32 + jq];
            #pragma unroll
            for (int gi = 0; gi < 2; gi++)
                #pragma unroll
                for (int e = 0; e < 4; e++) {
                    const int ee = eg * 4 + e;
                    const float2 raw = *reinterpret_cast<const float2*>(
                        &s.B.f2h[(gi * 32 + ee) * 64 + kq * 2]);
                    const __half2 ha = *reinterpret_cast<const __half2*>(&raw.x);
                    const __half2 hb = *reinterpret_cast<const __half2*>(&raw.y);
                    const float2 xa = __half22float2(ha);
                    const float2 xb = __half22float2(hb);
                    FMA4(acc[gi][e], xa.x, wa);
                    FMA4(acc[gi][e], xa.y, wb);
                    FMA4(acc[gi][e], xb.x, wc);
                    FMA4(acc[gi][e], xb.y, wd);
                }
        }
        #pragma unroll
        for (int k2 = 0; k2 < 3; k2++) {
            const float4 wv = Wq[(128 + k2) * 32 + jq];
            #pragma unroll
            for (int gi = 0; gi < 2; gi++)
                #pragma unroll
                for (int e = 0; e < 4; e++) {
                    const float r = s.pos2l2[gi * 96 + (eg * 4 + e) * 3 + k2];
                    FMA4(acc[gi][e], r, wv);
                }
        }
        #pragma unroll
        for (int gi = 0; gi < 2; gi++) {
            float4 pv;
            pv.x = celu1(acc[gi][0][0]) + celu1(acc[gi][1][0]) + celu1(acc[gi][2][0]) + celu1(acc[gi][3][0]);
            pv.y = celu1(acc[gi][0][1]) + celu1(acc[gi][1][1]) + celu1(acc[gi][2][1]) + celu1(acc[gi][3][1]);
            pv.z = celu1(acc[gi][0][2]) + celu1(acc[gi][1][2]) + celu1(acc[gi][2][2]) + celu1(acc[gi][3][2]);
            pv.w = celu1(acc[gi][0][3]) + celu1(acc[gi][1][3]) + celu1(acc[gi][2][3]) + celu1(acc[gi][3][3]);
            reinterpret_cast<float4*>(&s.A.psum[gi * 1024 + eg * 128 + jq * 4])[0] = pv;
        }
    }
    __syncthreads();
    {
        const int gi = tid >> 7;
        const int j  = tid & 127;
        float sum = 0.0f;
        #pragma unroll
        for (int e = 0; e < 8; e++) sum += s.A.psum[gi * 1024 + e * 128 + j];
        s.gsum[gi * 128 + j] = sum;
    }
    __syncthreads();

    // stage 6: f = celu((gsum/32) @ W3g + b3g), both glimpses
    {
        const int j = tid;
        float s0 = 0.0f, s1 = 0.0f;
        #pragma unroll 8
        for (int k = 0; k < 128; k++) {
            const float w = W3g[k * 256 + j];
            s0 = fmaf(s.gsum[k],       w, s0);
            s1 = fmaf(s.gsum[128 + k], w, s1);
        }
        const float bj = b3g[j];
        const float f0 = celu1(fmaf(s0, 0.03125f, bj));
        const float f1 = celu1(fmaf(s1, 0.03125f, bj));
        s.fvec[j] = f0;
        s.fvec[256 + j] = f1;
        out[OFF_F + (size_t)g0 * 256 + j] = f0;
        out[OFF_F + (size_t)(g0 + 1) * 256 + j] = f1;
    }
    __syncthreads();

    // stage 7: out = f @ Wlin + blin, both glimpses
    {
        const int j = tid;
        const float bj = blin[j];
        float a0 = bj, a1 = bj;
        #pragma unroll 8
        for (int k = 0; k < 256; k++) {
            const float w = Wlin[k * 256 + j];
            a0 = fmaf(s.fvec[k],       w, a0);
            a1 = fmaf(s.fvec[256 + k], w, a1);
        }
        s.outv[j] = a0;
        s.outv[256 + j] = a1;
    }
    __syncthreads();

    if (tid < 128) {
        #pragma unroll
        for (int gi = 0; gi < 2; gi++) {
            const size_t g = g0 + gi;
            const float mu = s.outv[gi * 256 + tid];
            const float sg = s.outv[gi * 256 + 128 + tid];
            const float sigma = fmaxf(sg, 0.0f) + log1pf(__expf(-fabsf(sg)));
            const float z = fmaf(sigma, eps[g * 128 + tid], mu);
            out[OFF_MU    + g * 128 + tid] = mu;
            out[OFF_SIGMA + g * 128 + tid] = sigma;
            if (tid < 64) out[OFF_ZWHAT + g * 64 + tid] = z;
            else          out[OFF_ZMASK + g * 64 + (tid - 64)] = z;
        }
    }
}

extern "C" void kernel_launch(void* const* d_in, const int* in_sizes, int n_in,
                              void* d_out, int out_size)
{
    const float* rgb  = (const float*)d_in[0];
    const float* pos  = (const float*)d_in[1];
    const float* pos1 = (const float*)d_in[2];
    const float* pos2 = (const float*)d_in[3];
    const int*   oi0  = (const int*)  d_in[4];
    const int*   oi1  = (const int*)  d_in[5];
    const float* eps  = (const float*)d_in[7];
    const float* W1l  = (const float*)d_in[8];
    const float* b1l  = (const float*)d_in[9];
    const float* W1g  = (const float*)d_in[10];
    const float* b1g  = (const float*)d_in[11];
    const float* W2l  = (const float*)d_in[12];
    const float* b2l  = (const float*)d_in[13];
    const float* W2g  = (const float*)d_in[14];
    const float* b2g  = (const float*)d_in[15];
    const float* W3l  = (const float*)d_in[16];
    const float* b3l  = (const float*)d_in[17];
    const float* W3g  = (const float*)d_in[18];
    const float* b3g  = (const float*)d_in[19];
    const float* Wlin = (const float*)d_in[20];
    const float* blin = (const float*)d_in[21];
    float* out = (float*)d_out;

    cudaFuncSetAttribute(vae_fused_kernel,
                         cudaFuncAttributeMaxDynamicSharedMemorySize,
                         (int)sizeof(Smem));
    vae_fused_kernel<<<NG / 2, 256, sizeof(Smem)>>>(
        rgb, pos, pos1, pos2, oi0, oi1, eps,
        W1l, b1l, W1g, b1g, W2l, b2l, W2g, b2g,
        W3l, b3l, W3g, b3g, Wlin, blin, out);
}